// round 13
// baseline (speedup 1.0000x reference)
#include <cuda_runtime.h>

// STN bilinear sampler, v13 — v9 (strip dedup + __stcs) at 4-row granularity.
// x: [32,256,256,32] f32 NHWC ; theta: [32,6] f32 ; out: same shape.
// Layout: 8 threads/pixel, one float4 each (wavefront-optimal); 4 rows/thread.
// Finer strips -> more strips classified fully-clamped -> fewer gathers, and
// 2x the CTA count smooths the wave tail given mode work variance.

#define B_ 32
#define H_ 256
#define W_ 256
#define ROWS_ 4
#define STEP (2.0f / 255.0f)
#define FULL 0xFFFFFFFFu

struct Ctx {
    float t0, t1, t2, t3, t4, t5;
    float gx;
    int basep, cg, oy, obase;
};

// MODE bit0 = x-duplicated (x0c==x1c), bit1 = y-duplicated (y0c==y1c)
template <int MODE>
__device__ __forceinline__ void run_strip(const Ctx& c,
                                          const float4* __restrict__ xf,
                                          float4* __restrict__ out)
{
#pragma unroll
    for (int k = 0; k < ROWS_; k++) {
        float gy = -1.0f + (float)(c.oy + k) * STEP;

        // identical formula to reference: 0.5*(T·g + 1)*N, truncate toward zero
        float sx = 0.5f * (c.t0 * c.gx + c.t1 * gy + c.t2 + 1.0f) * (float)W_;
        float sy = 0.5f * (c.t3 * c.gx + c.t4 * gy + c.t5 + 1.0f) * (float)H_;

        int x0 = (int)sx;
        int y0 = (int)sy;

        int x0c = min(max(x0, 0), W_ - 1);
        int x1c = min(max(x0 + 1, 0), W_ - 1);
        int y0c = min(max(y0, 0), H_ - 1);
        int y1c = min(max(y0 + 1, 0), H_ - 1);

        float x0f = (float)x0c, x1f = (float)x1c;
        float y0f = (float)y0c, y1f = (float)y1c;

        float wa = (x1f - sx) * (y1f - sy);
        float wb = (x1f - sx) * (sy - y0f);
        float wc = (sx - x0f) * (y1f - sy);
        float wd = (sx - x0f) * (sy - y0f);

        int dx = (x1c - x0c) << 3;
        int ia = ((c.basep + (y0c << 8) + x0c) << 3) + c.cg;
        int ib = ((c.basep + (y1c << 8) + x0c) << 3) + c.cg;

        float4 pa = __ldg(xf + ia);
        float4 pb = (MODE & 2) ? pa : __ldg(xf + ib);
        float4 pc = (MODE & 1) ? pa : __ldg(xf + ia + dx);
        float4 pd = (MODE & 1) ? pb : ((MODE & 2) ? pc : __ldg(xf + ib + dx));

        float4 o;
        o.x = wa * pa.x + wb * pb.x + wc * pc.x + wd * pd.x;
        o.y = wa * pa.y + wb * pb.y + wc * pc.y + wd * pd.y;
        o.z = wa * pa.z + wb * pb.z + wc * pc.z + wd * pd.z;
        o.w = wa * pa.w + wb * pb.w + wc * pc.w + wd * pd.w;

        // streaming store: output is write-once, keep L2 for the gather set
        __stcs(out + c.obase + (k << 11), o);   // + k * W_ * 8
    }
}

__global__ __launch_bounds__(256) void stn_kernel(
    const float4* __restrict__ xf,
    const float* __restrict__ theta,
    float4* __restrict__ out)
{
    int gid = blockIdx.x * blockDim.x + threadIdx.x;   // [0, 2^22)
    Ctx c;
    c.cg  = gid & 7;
    int ox  = (gid >> 3) & 255;
    int oyq = (gid >> 11) & 63;
    int b   = gid >> 17;
    c.oy = oyq << 2;

    // theta via 3x LDG.64 (8B-aligned: b*24 bytes)
    const float2* t2p = (const float2*)(theta + b * 6);
    float2 q0 = __ldg(t2p + 0);
    float2 q1 = __ldg(t2p + 1);
    float2 q2 = __ldg(t2p + 2);
    c.t0 = q0.x; c.t1 = q0.y; c.t2 = q1.x;
    c.t3 = q1.y; c.t4 = q2.x; c.t5 = q2.y;

    c.gx = -1.0f + (float)ox * STEP;
    c.basep = b << 16;
    c.obase = ((c.basep + (c.oy << 8) + ox) << 3) + c.cg;

    // ---- strip classification via endpoint rows (sx,sy affine in oy) ----
    float gyA = -1.0f + (float)c.oy * STEP;
    float gyB = -1.0f + (float)(c.oy + ROWS_ - 1) * STEP;

    float sxA = 0.5f * (c.t0 * c.gx + c.t1 * gyA + c.t2 + 1.0f) * (float)W_;
    float syA = 0.5f * (c.t3 * c.gx + c.t4 * gyA + c.t5 + 1.0f) * (float)H_;
    float sxB = 0.5f * (c.t0 * c.gx + c.t1 * gyB + c.t2 + 1.0f) * (float)W_;
    float syB = 0.5f * (c.t3 * c.gx + c.t4 * gyB + c.t5 + 1.0f) * (float)H_;

    // conservative margins (fp rounding guard): claim dup only when certain
    bool xlo = (sxA <= -1.01f)  && (sxB <= -1.01f);
    bool xhi = (sxA >= 255.01f) && (sxB >= 255.01f);
    bool ylo = (syA <= -1.01f)  && (syB <= -1.01f);
    bool yhi = (syA >= 255.01f) && (syB >= 255.01f);

    bool ux = __all_sync(FULL, xlo) || __all_sync(FULL, xhi);
    bool uy = __all_sync(FULL, ylo) || __all_sync(FULL, yhi);

    if (ux) {
        if (uy) run_strip<3>(c, xf, out);
        else    run_strip<1>(c, xf, out);
    } else {
        if (uy) run_strip<2>(c, xf, out);
        else    run_strip<0>(c, xf, out);
    }
}

extern "C" void kernel_launch(void* const* d_in, const int* in_sizes, int n_in,
                              void* d_out, int out_size)
{
    const float4* x    = (const float4*)d_in[0];
    const float* theta = (const float*)d_in[1];
    float4* out = (float4*)d_out;

    int total_threads = B_ * (H_ / ROWS_) * W_ * 8;   // 4,194,304
    int block = 256;
    int grid = total_threads / block;                  // 16,384
    stn_kernel<<<grid, block>>>(x, theta, out);
}

// round 14
// speedup vs baseline: 1.0315x; 1.0315x over previous
#include <cuda_runtime.h>

// STN bilinear sampler, v14 — minimal-overhead composite (final family).
// x: [32,256,256,32] f32 NHWC ; theta: [32,6] f32 ; out: same shape.
// Layout: 8 threads/pixel, one float4 each (wavefront-optimal: each gather
// LDG.128 covers exactly 4 distinct 128B input lines per warp; stores fully
// coalesced). 8 rows/thread amortizes theta+decode; straight-line body (no
// votes, no pipeline, no branches) keeps regs ~32 and occupancy ~80%.

#define B_ 32
#define H_ 256
#define W_ 256
#define ROWS_ 8
#define STEP (2.0f / 255.0f)

__global__ __launch_bounds__(256) void stn_kernel(
    const float4* __restrict__ xf,
    const float* __restrict__ theta,
    float4* __restrict__ out)
{
    int gid = blockIdx.x * blockDim.x + threadIdx.x;   // [0, 2^21)
    int cg  = gid & 7;                 // channel group (float4 within pixel)
    int ox  = (gid >> 3) & 255;
    int oy8 = (gid >> 11) & 31;        // 8-row group index
    int b   = gid >> 16;               // batch
    int oy  = oy8 << 3;

    // theta via 3x LDG.64 (8B-aligned: b*24 bytes), uniform per batch
    const float2* t2p = (const float2*)(theta + b * 6);
    float2 q0 = __ldg(t2p + 0);
    float2 q1 = __ldg(t2p + 1);
    float2 q2 = __ldg(t2p + 2);
    float t0 = q0.x, t1 = q0.y, t2 = q1.x;
    float t3 = q1.y, t4 = q2.x, t5 = q2.y;

    float gx = -1.0f + (float)ox * STEP;
    int basep = b << 16;               // b * H*W
    int obase = ((basep + (oy << 8) + ox) << 3) + cg;

#pragma unroll
    for (int k = 0; k < ROWS_; k++) {
        float gy = -1.0f + (float)(oy + k) * STEP;

        // identical formula to reference: 0.5*(T·g + 1)*N, truncate toward zero
        float sx = 0.5f * (t0 * gx + t1 * gy + t2 + 1.0f) * (float)W_;
        float sy = 0.5f * (t3 * gx + t4 * gy + t5 + 1.0f) * (float)H_;

        int x0 = (int)sx;
        int y0 = (int)sy;

        int x0c = min(max(x0, 0), W_ - 1);
        int x1c = min(max(x0 + 1, 0), W_ - 1);
        int y0c = min(max(y0, 0), H_ - 1);
        int y1c = min(max(y0 + 1, 0), H_ - 1);

        float x0f = (float)x0c, x1f = (float)x1c;
        float y0f = (float)y0c, y1f = (float)y1c;

        float wa = (x1f - sx) * (y1f - sy);
        float wb = (x1f - sx) * (sy - y0f);
        float wc = (sx - x0f) * (y1f - sy);
        float wd = (sx - x0f) * (sy - y0f);

        // float4-unit indices; x1 column derived via dx (0 or 8)
        int dx = (x1c - x0c) << 3;
        int ia = ((basep + (y0c << 8) + x0c) << 3) + cg;
        int ib = ((basep + (y1c << 8) + x0c) << 3) + cg;

        float4 pa = __ldg(xf + ia);
        float4 pc = __ldg(xf + ia + dx);
        float4 pb = __ldg(xf + ib);
        float4 pd = __ldg(xf + ib + dx);

        float4 o;
        o.x = wa * pa.x + wb * pb.x + wc * pc.x + wd * pd.x;
        o.y = wa * pa.y + wb * pb.y + wc * pc.y + wd * pd.y;
        o.z = wa * pa.z + wb * pb.z + wc * pc.z + wd * pd.z;
        o.w = wa * pa.w + wb * pb.w + wc * pc.w + wd * pd.w;

        // streaming store: output is write-once, keep L2 for the gather set
        __stcs(out + obase + (k << 11), o);   // + k * W_ * 8
    }
}

extern "C" void kernel_launch(void* const* d_in, const int* in_sizes, int n_in,
                              void* d_out, int out_size)
{
    const float4* x    = (const float4*)d_in[0];
    const float* theta = (const float*)d_in[1];
    float4* out = (float4*)d_out;

    int total_threads = B_ * (H_ / ROWS_) * W_ * 8;   // 2,097,152
    int block = 256;
    int grid = total_threads / block;                  // 8,192
    stn_kernel<<<grid, block>>>(x, theta, out);
}

// round 15
// speedup vs baseline: 1.0369x; 1.0052x over previous
#include <cuda_runtime.h>

// STN bilinear sampler — FINAL (v5, measured-best wallclock 66.0us; re-bench).
// x: [32,256,256,32] f32 NHWC ; theta: [32,6] f32 ; out: same shape.
// Layout (wavefront-optimal): 8 threads/pixel, one float4 each ->
// each gather LDG.128 covers exactly 4 distinct 128B input lines per warp.
// One thread covers EIGHT output rows; depth-2 software pipeline; streaming
// stores keep L2 reserved for the gather working set.

#define B_ 32
#define H_ 256
#define W_ 256
#define ROWS_ 8
#define STEP (2.0f / 255.0f)

struct Samp {
    float wa, wb, wc, wd;
    int ia, ib, dx;
};

__device__ __forceinline__ Samp make_samp(
    float gx, float gy,
    float t0, float t1, float t2, float t3, float t4, float t5,
    int basep, int cg)
{
    // identical formula to reference: 0.5*(T·g + 1)*N, truncate toward zero
    float sx = 0.5f * (t0 * gx + t1 * gy + t2 + 1.0f) * (float)W_;
    float sy = 0.5f * (t3 * gx + t4 * gy + t5 + 1.0f) * (float)H_;

    int x0 = (int)sx;
    int y0 = (int)sy;

    int x0c = min(max(x0, 0), W_ - 1);
    int x1c = min(max(x0 + 1, 0), W_ - 1);
    int y0c = min(max(y0, 0), H_ - 1);
    int y1c = min(max(y0 + 1, 0), H_ - 1);

    float x0f = (float)x0c, x1f = (float)x1c;
    float y0f = (float)y0c, y1f = (float)y1c;

    Samp s;
    s.wa = (x1f - sx) * (y1f - sy);
    s.wb = (x1f - sx) * (sy - y0f);
    s.wc = (sx - x0f) * (y1f - sy);
    s.wd = (sx - x0f) * (sy - y0f);
    s.dx = (x1c - x0c) << 3;
    s.ia = ((basep + (y0c << 8) + x0c) << 3) + cg;
    s.ib = ((basep + (y1c << 8) + x0c) << 3) + cg;
    return s;
}

__global__ __launch_bounds__(256) void stn_kernel(
    const float4* __restrict__ xf,
    const float* __restrict__ theta,
    float4* __restrict__ out)
{
    int gid = blockIdx.x * blockDim.x + threadIdx.x;   // [0, B*(H/8)*W*8)
    int cg  = gid & 7;                 // channel group (float4 within pixel)
    int ox  = (gid >> 3) & 255;
    int oy8 = (gid >> 11) & 31;        // 8-row group index
    int b   = gid >> 16;               // batch
    int oy  = oy8 << 3;

    // affine params (uniform per batch, L1 broadcast) — amortized over 8 rows
    const float* t = theta + b * 6;
    float t0 = __ldg(t + 0), t1 = __ldg(t + 1), t2 = __ldg(t + 2);
    float t3 = __ldg(t + 3), t4 = __ldg(t + 4), t5 = __ldg(t + 5);

    float gx = -1.0f + (float)ox * STEP;
    int basep = b << 16;               // b * H*W
    int obase = ((basep + (oy << 8) + ox) << 3) + cg;

    // ---- depth-2 software pipeline ----
    Samp s[2];
    float4 pa[2], pb[2], pc[2], pd[2];

    {
        float gy0 = -1.0f + (float)oy * STEP;
        s[0] = make_samp(gx, gy0, t0, t1, t2, t3, t4, t5, basep, cg);
        pa[0] = __ldg(xf + s[0].ia);
        pc[0] = __ldg(xf + s[0].ia + s[0].dx);
        pb[0] = __ldg(xf + s[0].ib);
        pd[0] = __ldg(xf + s[0].ib + s[0].dx);
    }

#pragma unroll
    for (int k = 0; k < ROWS_; k++) {
        int cur = k & 1, nxt = cur ^ 1;

        if (k < ROWS_ - 1) {
            float gy = -1.0f + (float)(oy + k + 1) * STEP;
            s[nxt] = make_samp(gx, gy, t0, t1, t2, t3, t4, t5, basep, cg);
            pa[nxt] = __ldg(xf + s[nxt].ia);
            pc[nxt] = __ldg(xf + s[nxt].ia + s[nxt].dx);
            pb[nxt] = __ldg(xf + s[nxt].ib);
            pd[nxt] = __ldg(xf + s[nxt].ib + s[nxt].dx);
        }

        float4 o;
        o.x = s[cur].wa * pa[cur].x + s[cur].wb * pb[cur].x
            + s[cur].wc * pc[cur].x + s[cur].wd * pd[cur].x;
        o.y = s[cur].wa * pa[cur].y + s[cur].wb * pb[cur].y
            + s[cur].wc * pc[cur].y + s[cur].wd * pd[cur].y;
        o.z = s[cur].wa * pa[cur].z + s[cur].wb * pb[cur].z
            + s[cur].wc * pc[cur].z + s[cur].wd * pd[cur].z;
        o.w = s[cur].wa * pa[cur].w + s[cur].wb * pb[cur].w
            + s[cur].wc * pc[cur].w + s[cur].wd * pd[cur].w;

        // streaming store: output is write-once, keep L2 for the gather set
        __stcs(out + obase + (k << 11), o);   // k * W_ * 8
    }
}

extern "C" void kernel_launch(void* const* d_in, const int* in_sizes, int n_in,
                              void* d_out, int out_size)
{
    const float4* x    = (const float4*)d_in[0];
    const float* theta = (const float*)d_in[1];
    float4* out = (float4*)d_out;

    int total_threads = B_ * (H_ / ROWS_) * W_ * 8;   // 2,097,152
    int block = 256;
    int grid = total_threads / block;                  // 8,192
    stn_kernel<<<grid, block>>>(x, theta, out);
}